// round 5
// baseline (speedup 1.0000x reference)
#include <cuda_runtime.h>
#include <cuda_bf16.h>
#include <cstdint>

// ---------------------------------------------------------------------------
// Problem constants
// ---------------------------------------------------------------------------
constexpr int B_   = 8192;
constexpr int T_   = 658;
constexpr int I_   = 7;
constexpr int D1_  = 1024;
constexpr int D2_  = 512;
constexpr int D3_  = 128;
constexpr int XWT  = 688;            // T_ padded for scan prefetch overrun
constexpr int TPAD = 672;            // T_ padded to multiple of 32 (GEMM1 K)

// ---------------------------------------------------------------------------
// Scratch (device globals zero-init; padded regions either rewritten or 0)
// ---------------------------------------------------------------------------
__device__ float          g_xw [(size_t)XWT * B_];     // [T,B] fp32 (rows >= T_ stay 0)
__device__ __nv_bfloat16  g_ath[(size_t)B_ * TPAD];    // hs^T hi  [B,TPAD]
__device__ __nv_bfloat16  g_atl[(size_t)B_ * TPAD];    // hs^T lo

__device__ __nv_bfloat16  g_w1h[(size_t)D1_ * TPAD], g_w1l[(size_t)D1_ * TPAD];
__device__ __nv_bfloat16  g_w2h[(size_t)D2_ * D1_ ], g_w2l[(size_t)D2_ * D1_ ];
__device__ __nv_bfloat16  g_w3h[(size_t)D3_ * D2_ ], g_w3l[(size_t)D3_ * D2_ ];
__device__ __nv_bfloat16  g_w4h[(size_t)T_  * D3_ ], g_w4l[(size_t)T_  * D3_ ];

__device__ __nv_bfloat16  g_y1h[(size_t)B_ * D1_], g_y1l[(size_t)B_ * D1_];
__device__ __nv_bfloat16  g_y2h[(size_t)B_ * D2_], g_y2l[(size_t)B_ * D2_];
__device__ __nv_bfloat16  g_y3h[(size_t)B_ * D3_], g_y3l[(size_t)B_ * D3_];

// ---------------------------------------------------------------------------
// PTX helpers (base-target ISA only: ldmatrix / mma.sync / cp.async)
// ---------------------------------------------------------------------------
__device__ __forceinline__ uint32_t smem_u32(const void* p) {
    uint32_t a;
    asm("{ .reg .u64 t; cvta.to.shared.u64 t, %1; cvt.u32.u64 %0, t; }" : "=r"(a) : "l"(p));
    return a;
}

__device__ __forceinline__ void cp16(uint32_t dst, const void* src, int srcsize) {
    asm volatile("cp.async.cg.shared.global [%0], [%1], 16, %2;"
                 :: "r"(dst), "l"(src), "r"(srcsize));
}
#define CP_COMMIT() asm volatile("cp.async.commit_group;" ::: "memory")
#define CP_WAIT(n)  asm volatile("cp.async.wait_group %0;" :: "n"(n) : "memory")

#define LDSM4(r, a)                                                             \
    asm volatile("ldmatrix.sync.aligned.m8n8.x4.shared.b16 {%0,%1,%2,%3}, [%4];"\
                 : "=r"((r)[0]), "=r"((r)[1]), "=r"((r)[2]), "=r"((r)[3])       \
                 : "r"(a))

__device__ __forceinline__ void mma16816(float* d, const uint32_t* a,
                                         uint32_t b0, uint32_t b1) {
    asm volatile("mma.sync.aligned.m16n8k16.row.col.f32.bf16.bf16.f32 "
                 "{%0,%1,%2,%3}, {%4,%5,%6,%7}, {%8,%9}, {%0,%1,%2,%3};"
                 : "+f"(d[0]), "+f"(d[1]), "+f"(d[2]), "+f"(d[3])
                 : "r"(a[0]), "r"(a[1]), "r"(a[2]), "r"(a[3]), "r"(b0), "r"(b1));
}

// ---------------------------------------------------------------------------
// Stage 1: xw[t,b] = dot(x[b,t,:], W_ih) + b_ih + b_hh   ([T,B] fp32)
// ---------------------------------------------------------------------------
__global__ void proj_kernel(const float* __restrict__ x,
                            const float* __restrict__ W_ih,
                            const float* __restrict__ b_ih,
                            const float* __restrict__ b_hh) {
    __shared__ float xs[32][225];
    const int t0 = blockIdx.x * 32;
    const int b0 = blockIdx.y * 32;
    const int tid = threadIdx.x;
    const int tlim = min(32, T_ - t0);
    const int nfl = tlim * I_;

    for (int i = tid; i < 32 * 224; i += 256) {
        int bl = i / 224;
        int off = i - bl * 224;
        float v = 0.f;
        if (off < nfl) v = x[((size_t)(b0 + bl) * T_ + t0) * I_ + off];
        xs[bl][off] = v;
    }
    __syncthreads();

    float w[7];
#pragma unroll
    for (int j = 0; j < 7; ++j) w[j] = W_ih[j];
    const float bias = b_ih[0] + b_hh[0];

    for (int i = tid; i < 1024; i += 256) {
        int bl = i & 31;
        int tl = i >> 5;
        if (tl < tlim) {
            const float* row = &xs[bl][tl * 7];
            float s = bias;
#pragma unroll
            for (int j = 0; j < 7; ++j) s = fmaf(row[j], w[j], s);
            g_xw[(size_t)(t0 + tl) * B_ + (b0 + bl)] = s;
        }
    }
}

// ---------------------------------------------------------------------------
// Stage 2: scalar tanh recurrence -> g_ath/g_atl [B,TPAD] bf16 hi/lo DIRECT
//   (transpose fused: 32-step chunks staged in smem as packed hi|lo uint32,
//    flushed coalesced along t). Pad steps t in [T_,TPAD) produce junk h, but
//    those A-columns multiply zero-padded weight columns in GEMM1 -> harmless.
//   Hidden output = h at t == T_-1 (NOT loop-exit value).
// ---------------------------------------------------------------------------
__device__ __forceinline__ float tanh_fast(float xv) {
    float ax = fabsf(xv);
    float e = __expf(-2.0f * ax);
    float r = __fdividef(1.0f - e, 1.0f + e);
    return copysignf(r, xv);
}

__device__ __forceinline__ uint32_t pack_hilo(float v) {
    __nv_bfloat16 h = __float2bfloat16(v);
    __nv_bfloat16 l = __float2bfloat16(v - __bfloat162float(h));
    return (uint32_t)__bfloat16_as_ushort(h) | ((uint32_t)__bfloat16_as_ushort(l) << 16);
}

__global__ void __launch_bounds__(256)
scan_kernel(const float* __restrict__ h0,
            const float* __restrict__ W_hh,
            float* __restrict__ hid) {
    __shared__ uint32_t sh[256][33];   // (r+j)%32 banking: conflict-free
    const int tid = threadIdx.x;
    const int b0 = blockIdx.x * 256;
    const int b  = b0 + tid;

    const float whh = W_hh[0];
    const float* xp = g_xw + b;
    float h = h0[b];
    float hT = h;

    float bufA[16], bufB[16];
#pragma unroll
    for (int j = 0; j < 16; ++j) bufA[j] = xp[(size_t)j * B_];

    for (int tc = 0; tc < TPAD; tc += 32) {
#pragma unroll
        for (int j = 0; j < 16; ++j) bufB[j] = xp[(size_t)(tc + 16 + j) * B_];
#pragma unroll
        for (int j = 0; j < 16; ++j) {
            h = tanh_fast(fmaf(h, whh, bufA[j]));
            sh[tid][j] = pack_hilo(h);
            if (tc + j == T_ - 1) hT = h;
        }
#pragma unroll
        for (int j = 0; j < 16; ++j) bufA[j] = xp[(size_t)(tc + 32 + j) * B_];  // max 687 < XWT
#pragma unroll
        for (int j = 0; j < 16; ++j) {
            h = tanh_fast(fmaf(h, whh, bufB[j]));
            sh[tid][16 + j] = pack_hilo(h);
            if (tc + 16 + j == T_ - 1) hT = h;
        }
        __syncthreads();
        // coalesced flush: warp writes 32 consecutive t of one b-row
#pragma unroll
        for (int it = 0; it < 32; ++it) {
            int lin = it * 256 + tid;
            int r = lin >> 5, j = lin & 31;
            uint32_t v = sh[r][j];
            size_t o = (size_t)(b0 + r) * TPAD + tc + j;
            g_ath[o] = __ushort_as_bfloat16((uint16_t)(v & 0xffff));
            g_atl[o] = __ushort_as_bfloat16((uint16_t)(v >> 16));
        }
        __syncthreads();
    }
    if (hid) hid[b] = hT;
}

// ---------------------------------------------------------------------------
// Weight conversion: fp32 [R,K] -> bf16 hi/lo [R,Kp] (pad stays 0)
// ---------------------------------------------------------------------------
__global__ void cvt_w(const float* __restrict__ src,
                      __nv_bfloat16* __restrict__ hi,
                      __nv_bfloat16* __restrict__ lo,
                      int R, int K, int Kp) {
    int i = blockIdx.x * blockDim.x + threadIdx.x;
    if (i < R * K) {
        int r = i / K, k = i - r * K;
        float v = src[i];
        __nv_bfloat16 h = __float2bfloat16(v);
        hi[(size_t)r * Kp + k] = h;
        lo[(size_t)r * Kp + k] = __float2bfloat16(v - __bfloat162float(h));
    }
}

// ---------------------------------------------------------------------------
// mma.sync GEMM: C[M,N] = act(A * B^T + bias), 3-term bf16 hi/lo split.
//   A: [M,K] bf16 hi/lo row-major.  B: [N,K] bf16 hi/lo K-major.
//   CTA 128x128, BK=32, cp.async double buffer, warp tile 32x64.
//   __launch_bounds__(256,2): 2 CTAs/SM (160KB smem, <=128 regs).
// ---------------------------------------------------------------------------
constexpr int PITCH = 80;
constexpr int MATSZ = 128 * PITCH;        // 10240
constexpr int STAGE = 4 * MATSZ;          // 40960
constexpr int GEMM_SMEM = 2 * STAGE;      // 81920

__device__ __forceinline__ void load_stage(
        uint32_t sbase, int stage, int k0, int tid,
        const __nv_bfloat16* Ah, const __nv_bfloat16* Al,
        const __nv_bfloat16* Bh, const __nv_bfloat16* Bl,
        int K, int N, int bm, int bn) {
#pragma unroll
    for (int it = 0; it < 8; ++it) {
        int i = tid + it * 256;
        int mat = i >> 9;          // 0:Ah 1:Al 2:Bh 3:Bl
        int row = (i >> 2) & 127;
        int seg = i & 3;
        uint32_t dst = sbase + stage * STAGE + mat * MATSZ + row * PITCH + seg * 16;
        const __nv_bfloat16* src;
        int size = 16;
        if (mat < 2) {
            src = (mat == 0 ? Ah : Al) + (size_t)(bm + row) * K + k0 + seg * 8;
        } else {
            const __nv_bfloat16* base = (mat == 2 ? Bh : Bl);
            int n = bn + row;
            if (n < N) {
                src = base + (size_t)n * K + k0 + seg * 8;
            } else {
                src = base + k0 + seg * 8;
                size = 0;
            }
        }
        cp16(dst, src, size);
    }
}

template <bool RELU, bool F32OUT>
__global__ void __launch_bounds__(256, 2)
gemm_mma(const __nv_bfloat16* __restrict__ Ah, const __nv_bfloat16* __restrict__ Al,
         const __nv_bfloat16* __restrict__ Bh, const __nv_bfloat16* __restrict__ Bl,
         const float* __restrict__ bias,
         __nv_bfloat16* __restrict__ Oh, __nv_bfloat16* __restrict__ Ol,
         float* __restrict__ Of,
         int K, int N, int strideO) {
    extern __shared__ char smem[];
    const uint32_t sbase = smem_u32(smem);
    const int tid = threadIdx.x;
    const int lane = tid & 31;
    const int wid = tid >> 5;
    const int wm = wid & 3;         // 4 warps over M
    const int wn = wid >> 2;        // 2 warps over N
    const int bm = blockIdx.x * 128;
    const int bn = blockIdx.y * 128;
    const int nk = K >> 5;

    float acc[2][8][4];
#pragma unroll
    for (int i = 0; i < 2; ++i)
#pragma unroll
        for (int j = 0; j < 8; ++j)
#pragma unroll
            for (int q = 0; q < 4; ++q) acc[i][j][q] = 0.f;

    const uint32_t a_addr = sbase + (wm * 32 + (lane & 15)) * PITCH + (lane >> 4) * 16;
    const uint32_t b_addr = sbase + 2 * MATSZ +
        (wn * 64 + (lane & 7) + ((lane >> 4) * 8)) * PITCH + ((lane >> 3) & 1) * 16;

    load_stage(sbase, 0, 0, tid, Ah, Al, Bh, Bl, K, N, bm, bn);
    CP_COMMIT();

    for (int kc = 0; kc < nk; ++kc) {
        __syncthreads();
        if (kc + 1 < nk) {
            load_stage(sbase, (kc + 1) & 1, (kc + 1) * 32, tid, Ah, Al, Bh, Bl, K, N, bm, bn);
            CP_COMMIT();
            CP_WAIT(1);
        } else {
            CP_WAIT(0);
        }
        __syncthreads();

        const uint32_t st = ((kc & 1) ? STAGE : 0);
#pragma unroll
        for (int kk = 0; kk < 2; ++kk) {
            const uint32_t ko = kk * 32;
            uint32_t aH[2][4], aL[2][4];
#pragma unroll
            for (int mi = 0; mi < 2; ++mi) {
                LDSM4(aH[mi], a_addr + st + mi * (16 * PITCH) + ko);
                LDSM4(aL[mi], a_addr + st + MATSZ + mi * (16 * PITCH) + ko);
            }
            uint32_t bH[4][4], bL[4][4];
#pragma unroll
            for (int np = 0; np < 4; ++np) {
                LDSM4(bH[np], b_addr + st + np * (16 * PITCH) + ko);
                LDSM4(bL[np], b_addr + st + MATSZ + np * (16 * PITCH) + ko);
            }
#pragma unroll
            for (int mi = 0; mi < 2; ++mi)
#pragma unroll
                for (int np = 0; np < 4; ++np) {
                    float* d0 = acc[mi][np * 2];
                    float* d1 = acc[mi][np * 2 + 1];
                    mma16816(d0, aH[mi], bH[np][0], bH[np][1]);
                    mma16816(d0, aH[mi], bL[np][0], bL[np][1]);
                    mma16816(d0, aL[mi], bH[np][0], bH[np][1]);
                    mma16816(d1, aH[mi], bH[np][2], bH[np][3]);
                    mma16816(d1, aH[mi], bL[np][2], bL[np][3]);
                    mma16816(d1, aL[mi], bH[np][2], bH[np][3]);
                }
        }
    }

    // Epilogue
    const int g = lane >> 2, tig = lane & 3;
#pragma unroll
    for (int mi = 0; mi < 2; ++mi) {
#pragma unroll
        for (int np = 0; np < 4; ++np) {
#pragma unroll
            for (int c = 0; c < 2; ++c) {
                int col = bn + wn * 64 + np * 16 + c * 8 + 2 * tig;
                float b0 = 0.f, b1 = 0.f;
                if (col < N) { b0 = bias[col]; b1 = bias[col + 1]; }
                float* a = acc[mi][np * 2 + c];
                int r0 = bm + wm * 32 + mi * 16 + g;
                float v00 = a[0] + b0, v01 = a[1] + b1;
                float v10 = a[2] + b0, v11 = a[3] + b1;
                if (RELU) {
                    v00 = fmaxf(v00, 0.f); v01 = fmaxf(v01, 0.f);
                    v10 = fmaxf(v10, 0.f); v11 = fmaxf(v11, 0.f);
                }
                if (F32OUT) {
                    if (col < N) {
                        *(float2*)(Of + (size_t)r0 * strideO + col) = make_float2(v00, v01);
                        *(float2*)(Of + (size_t)(r0 + 8) * strideO + col) = make_float2(v10, v11);
                    }
                } else {
                    __nv_bfloat16 h00 = __float2bfloat16(v00), h01 = __float2bfloat16(v01);
                    __nv_bfloat16 h10 = __float2bfloat16(v10), h11 = __float2bfloat16(v11);
                    __nv_bfloat16 l00 = __float2bfloat16(v00 - __bfloat162float(h00));
                    __nv_bfloat16 l01 = __float2bfloat16(v01 - __bfloat162float(h01));
                    __nv_bfloat16 l10 = __float2bfloat16(v10 - __bfloat162float(h10));
                    __nv_bfloat16 l11 = __float2bfloat16(v11 - __bfloat162float(h11));
                    uint32_t ph0 = (uint32_t)__bfloat16_as_ushort(h00) | ((uint32_t)__bfloat16_as_ushort(h01) << 16);
                    uint32_t pl0 = (uint32_t)__bfloat16_as_ushort(l00) | ((uint32_t)__bfloat16_as_ushort(l01) << 16);
                    uint32_t ph1 = (uint32_t)__bfloat16_as_ushort(h10) | ((uint32_t)__bfloat16_as_ushort(h11) << 16);
                    uint32_t pl1 = (uint32_t)__bfloat16_as_ushort(l10) | ((uint32_t)__bfloat16_as_ushort(l11) << 16);
                    *(uint32_t*)(Oh + (size_t)r0 * strideO + col) = ph0;
                    *(uint32_t*)(Ol + (size_t)r0 * strideO + col) = pl0;
                    *(uint32_t*)(Oh + (size_t)(r0 + 8) * strideO + col) = ph1;
                    *(uint32_t*)(Ol + (size_t)(r0 + 8) * strideO + col) = pl1;
                }
            }
        }
    }
}

// ---------------------------------------------------------------------------
extern "C" void kernel_launch(void* const* d_in, const int* in_sizes, int n_in,
                              void* d_out, int out_size) {
    const float* x    = (const float*)d_in[0];
    const float* h0   = (const float*)d_in[1];
    const float* W_ih = (const float*)d_in[2];
    const float* W_hh = (const float*)d_in[3];
    const float* b_ih = (const float*)d_in[4];
    const float* b_hh = (const float*)d_in[5];
    const float* w1   = (const float*)d_in[6];
    const float* b1   = (const float*)d_in[7];
    const float* w2   = (const float*)d_in[8];
    const float* b2   = (const float*)d_in[9];
    const float* w3   = (const float*)d_in[10];
    const float* b3   = (const float*)d_in[11];
    const float* w4   = (const float*)d_in[12];
    const float* b4   = (const float*)d_in[13];
    float* out = (float*)d_out;
    float* hid = (out_size >= B_ * T_ + B_) ? out + (size_t)B_ * T_ : nullptr;

    __nv_bfloat16 *ath, *atl, *w1h, *w1l, *w2h, *w2l, *w3h, *w3l, *w4h, *w4l;
    __nv_bfloat16 *y1h, *y1l, *y2h, *y2l, *y3h, *y3l;
    cudaGetSymbolAddress((void**)&ath, g_ath); cudaGetSymbolAddress((void**)&atl, g_atl);
    cudaGetSymbolAddress((void**)&w1h, g_w1h); cudaGetSymbolAddress((void**)&w1l, g_w1l);
    cudaGetSymbolAddress((void**)&w2h, g_w2h); cudaGetSymbolAddress((void**)&w2l, g_w2l);
    cudaGetSymbolAddress((void**)&w3h, g_w3h); cudaGetSymbolAddress((void**)&w3l, g_w3l);
    cudaGetSymbolAddress((void**)&w4h, g_w4h); cudaGetSymbolAddress((void**)&w4l, g_w4l);
    cudaGetSymbolAddress((void**)&y1h, g_y1h); cudaGetSymbolAddress((void**)&y1l, g_y1l);
    cudaGetSymbolAddress((void**)&y2h, g_y2h); cudaGetSymbolAddress((void**)&y2l, g_y2l);
    cudaGetSymbolAddress((void**)&y3h, g_y3h); cudaGetSymbolAddress((void**)&y3l, g_y3l);

    cudaFuncSetAttribute(gemm_mma<true,  false>, cudaFuncAttributeMaxDynamicSharedMemorySize, GEMM_SMEM);
    cudaFuncSetAttribute(gemm_mma<false, true >, cudaFuncAttributeMaxDynamicSharedMemorySize, GEMM_SMEM);

    // Order chosen so launch index 3 (ncu capture slot) == gemm1.
    // 1) input projection (fp32, [T,B])
    proj_kernel<<<dim3((T_ + 31) / 32, B_ / 32), 256>>>(x, W_ih, b_ih, b_hh);
    // 2) recurrence -> g_ath/g_atl [B,TPAD] bf16 hi/lo (transpose fused), hidden -> out tail
    scan_kernel<<<B_ / 256, 256>>>(h0, W_hh, hid);
    // 3) w1 conversion, then GEMM1 immediately (capture slot)
    cvt_w<<<(D1_ * T_  + 255) / 256, 256>>>(w1, w1h, w1l, D1_, T_,  TPAD);
    gemm_mma<true, false><<<dim3(B_ / 128, D1_ / 128), 256, GEMM_SMEM>>>(
        ath, atl, w1h, w1l, b1, y1h, y1l, nullptr, TPAD, D1_, D1_);
    // 4) layer 2
    cvt_w<<<(D2_ * D1_ + 255) / 256, 256>>>(w2, w2h, w2l, D2_, D1_, D1_);
    gemm_mma<true, false><<<dim3(B_ / 128, D2_ / 128), 256, GEMM_SMEM>>>(
        y1h, y1l, w2h, w2l, b2, y2h, y2l, nullptr, D1_, D2_, D2_);
    // 5) layer 3
    cvt_w<<<(D3_ * D2_ + 255) / 256, 256>>>(w3, w3h, w3l, D3_, D2_, D2_);
    gemm_mma<true, false><<<dim3(B_ / 128, D3_ / 128), 256, GEMM_SMEM>>>(
        y2h, y2l, w3h, w3l, b3, y3h, y3l, nullptr, D2_, D3_, D3_);
    // 6) layer 4 (fp32 out, N=658 masked)
    cvt_w<<<(T_  * D3_ + 255) / 256, 256>>>(w4, w4h, w4l, T_,  D3_, D3_);
    gemm_mma<false, true><<<dim3(B_ / 128, (T_ + 127) / 128), 256, GEMM_SMEM>>>(
        y3h, y3l, w4h, w4l, b4, nullptr, nullptr, out, D3_, T_, T_);
}